// round 14
// baseline (speedup 1.0000x reference)
#include <cuda_runtime.h>

#define NT 128
#define RPC 256                 // rows per CTA (2 per thread)
#define STEPS 15
#define SPEED 5.0f
#define NCOLS_IN 18
#define NCOLS_OUT 178
#define CBUF 14                 // 10 staged cols + 4 pad (even: float2-aligned)
#define BUFO (RPC * CBUF)       // float offset of buffer B
#define SMEM_BYTES (2 * RPC * CBUF * 4)

template <int NC>
__device__ __forceinline__ void flush2(float* __restrict__ out,
                                       const float* __restrict__ stage,
                                       int R0, int rows_blk, int base_col, int t)
{
    constexpr int NC2 = NC / 2;          // NC even
    const unsigned total = (unsigned)rows_blk * NC2;
    for (unsigned idx = t; idx < total; idx += NT) {
        unsigned r = idx / NC2;
        unsigned k = idx - r * NC2;
        float2 v = *(const float2*)(stage + r * CBUF + 2 * k);
        *(float2*)(out + (long long)(R0 + r) * NCOLS_OUT + base_col + 2 * k) = v;
    }
}

__global__ void __launch_bounds__(NT, 7) prog_kernel(
    const float* __restrict__ x,
    const float* __restrict__ c1w, const float* __restrict__ c1b,
    const float* __restrict__ c2w, const float* __restrict__ c2b,
    const float* __restrict__ l1w, const float* __restrict__ l1b,
    const float* __restrict__ l2w, const float* __restrict__ l2b,
    float* __restrict__ out, int n)
{
    extern __shared__ float s_rows[];   // 2 ping-pong staging buffers (1 step each)

    // Pair-packed weights: 16 blocks of 20 floats (80B, 16B-aligned).
    __shared__ float s_w[16 * 20];
    __shared__ float s_cb[12];

    const int t = threadIdx.x;
    if (t < 32) {
        const int j = t;
        const int base = 20 * (j >> 1) + 10 * (j & 1);
        s_w[base + 0] = l1w[0 * 32 + j];
        s_w[base + 1] = l1w[1 * 32 + j];
        s_w[base + 2] = l1w[2 * 32 + j];
        s_w[base + 3] = l1w[3 * 32 + j];
        s_w[base + 4] = l1b[j];
        s_w[base + 5] = l2w[5 * j + 0];
        s_w[base + 6] = l2w[5 * j + 1];
        s_w[base + 7] = l2w[5 * j + 2];
        s_w[base + 8] = l2w[5 * j + 3];
        s_w[base + 9] = l2w[5 * j + 4];
    } else if (t < 64) {
        const int u = t - 32;
        if (u < 12) {
            float v;
            if      (u == 0) v = c1w[0];
            else if (u == 1) v = c1w[1];
            else if (u == 2) v = c1b[0];
            else if (u == 3) v = c2w[0];
            else if (u == 4) v = c2w[1];
            else if (u == 5) v = c2b[0];
            else if (u < 11) v = l2b[u - 6];
            else             v = 0.0f;
            s_cb[u] = v;
        }
    }
    __syncthreads();

    const int R0 = blockIdx.x * RPC;
    int rows_blk = n - R0; if (rows_blk > RPC) rows_blk = RPC;

    const float c1w0 = s_cb[0], c1w1 = s_cb[1], c1b0 = s_cb[2];
    const float c2w0 = s_cb[3], c2w1 = s_cb[4], c2b0 = s_cb[5];
    const float l2b0 = s_cb[6], l2b1 = s_cb[7], l2b2 = s_cb[8];
    const float l2b3 = s_cb[9], l2b4 = s_cb[10];

    float s0[2], s1[2], s2[2], s3[2], s4[2], s5[2], s6[2], s7[2], s8[2],
          s9[2], s10[2], s11[2], s12[2], s13[2], s14[2], s15[2], s16[2], s17[2];
    float* myA[2];
    float* myB[2];

    #pragma unroll
    for (int r = 0; r < 2; r++) {
        const int lr = t + r * NT;
        const int row = R0 + ((lr < rows_blk) ? lr : 0);
        myA[r] = s_rows + lr * CBUF;
        myB[r] = myA[r] + BUFO;
        const float* xr = x + (long long)row * NCOLS_IN;
        float2 v0 = *(const float2*)(xr + 0);
        float2 v1 = *(const float2*)(xr + 2);
        float2 v2 = *(const float2*)(xr + 4);
        float2 v3 = *(const float2*)(xr + 6);
        float2 v4 = *(const float2*)(xr + 8);
        float2 v8 = *(const float2*)(xr + 16);
        s0[r] = v0.x; s1[r] = v0.y; s2[r] = v1.x; s3[r] = v1.y;
        s4[r] = v2.x; s5[r] = v2.y; s6[r] = v3.x; s7[r] = v3.y;
        s8[r] = v4.x; s9[r] = v4.y; s17[r] = v8.y;
        float d13 = s1[r] - s3[r], d24 = s2[r] - s4[r];
        s10[r] = fmaf(d13, d13, d24 * d24);
        s11[r] = s12[r] = s13[r] = s14[r] = s15[r] = s16[r] = 0.0f;
    }

    auto stash = [&](int r, float* slot) {
        *(float2*)(slot + 0) = make_float2(s10[r], s1[r]);
        *(float2*)(slot + 2) = make_float2(s2[r], s3[r]);
        *(float2*)(slot + 4) = make_float2(s4[r], s5[r]);
        *(float2*)(slot + 6) = make_float2(s6[r], s7[r]);
        *(float2*)(slot + 8) = make_float2(s8[r], s17[r]);
    };

    auto do_step = [&](float* sl0, float* sl1) {
        float h20[2], h21[2], h22[2], h23[2];
        float p0[2], p1[2], p2[2], p3[2], p4[2];

        #pragma unroll
        for (int r = 0; r < 2; r++) {
            const float f0 = s1[r], f1 = s2[r], f2 = s3[r], f3 = s4[r],
                        f4 = s9[r], f5 = s17[r];
            float h10 = fmaxf(fmaf(c1w1, f1, fmaf(c1w0, f0, c1b0)), 0.0f);
            float h11 = fmaxf(fmaf(c1w1, f2, fmaf(c1w0, f1, c1b0)), 0.0f);
            float h12 = fmaxf(fmaf(c1w1, f3, fmaf(c1w0, f2, c1b0)), 0.0f);
            float h13 = fmaxf(fmaf(c1w1, f4, fmaf(c1w0, f3, c1b0)), 0.0f);
            float h14 = fmaxf(fmaf(c1w1, f5, fmaf(c1w0, f4, c1b0)), 0.0f);
            h20[r] = fmaxf(fmaf(c2w1, h11, fmaf(c2w0, h10, c2b0)), 0.0f);
            h21[r] = fmaxf(fmaf(c2w1, h12, fmaf(c2w0, h11, c2b0)), 0.0f);
            h22[r] = fmaxf(fmaf(c2w1, h13, fmaf(c2w0, h12, c2b0)), 0.0f);
            h23[r] = fmaxf(fmaf(c2w1, h14, fmaf(c2w0, h13, c2b0)), 0.0f);
            p0[r] = l2b0; p1[r] = l2b1; p2[r] = l2b2; p3[r] = l2b3; p4[r] = l2b4;
        }

        #pragma unroll 8
        for (int q = 0; q < 16; q++) {
            const float4 a0 = *(const float4*)(s_w + 20 * q + 0);
            const float4 a1 = *(const float4*)(s_w + 20 * q + 4);
            const float4 a2 = *(const float4*)(s_w + 20 * q + 8);
            const float4 a3 = *(const float4*)(s_w + 20 * q + 12);
            const float4 a4 = *(const float4*)(s_w + 20 * q + 16);

            #pragma unroll
            for (int r = 0; r < 2; r++) {
                float h3a = fmaf(h23[r], a0.w,
                            fmaf(h22[r], a0.z,
                            fmaf(h21[r], a0.y,
                            fmaf(h20[r], a0.x, a1.x))));
                h3a = fmaxf(h3a, 0.0f);
                p0[r] = fmaf(h3a, a1.y, p0[r]);
                p1[r] = fmaf(h3a, a1.z, p1[r]);
                p2[r] = fmaf(h3a, a1.w, p2[r]);
                p3[r] = fmaf(h3a, a2.x, p3[r]);
                p4[r] = fmaf(h3a, a2.y, p4[r]);

                float h3b = fmaf(h23[r], a3.y,
                            fmaf(h22[r], a3.x,
                            fmaf(h21[r], a2.w,
                            fmaf(h20[r], a2.z, a3.z))));
                h3b = fmaxf(h3b, 0.0f);
                p0[r] = fmaf(h3b, a3.w, p0[r]);
                p1[r] = fmaf(h3b, a4.x, p1[r]);
                p2[r] = fmaf(h3b, a4.y, p2[r]);
                p3[r] = fmaf(h3b, a4.z, p3[r]);
                p4[r] = fmaf(h3b, a4.w, p4[r]);
            }
        }

        #pragma unroll
        for (int r = 0; r < 2; r++) {
            float q0 = 1.0f / (1.0f + expf(-p0[r]));
            float q1 = 1.0f / (1.0f + expf(-p1[r]));
            float q2 = 1.0f / (1.0f + expf(-p2[r]));
            float q3 = 1.0f / (1.0f + expf(-p3[r]));
            float q4 = 1.0f / (1.0f + expf(-p4[r]));

            s5[r] = q0; s6[r] = q1; s7[r] = q2; s8[r] = q3; s17[r] = q4;

            const float a = q1 - q0, b = q2 - q0, c = q3 - q0;
            const float d = q2 - q1, e = q3 - q1, f = q3 - q2;
            s11[r] = a; s12[r] = b; s13[r] = c;
            s14[r] = d; s15[r] = e; s16[r] = f;

            const float dx_c = (c <= 0.0f) ? 0.0f : SPEED;
            const float st_c = (c <= 0.0f) ? 0.0f : 3.0f;
            const float dx_f = (f <= 0.0f) ? 0.0f : SPEED;
            const float st_f = (f <= 0.0f) ? 2.0f : 3.0f;
            const float dx_e = (e <= 0.0f) ? -SPEED : SPEED;
            const float st_e = (e <= 0.0f) ? 1.0f : 3.0f;
            const float dx_b = (b <= 0.0f) ? dx_c : dx_f;
            const float st_b = (b <= 0.0f) ? st_c : st_f;
            const float dx_d = (d <= 0.0f) ? dx_e : dx_f;
            const float st_d = (d <= 0.0f) ? st_e : st_f;
            const float dx   = (a <= 0.0f) ? dx_b : dx_d;
            const float st   = (a <= 0.0f) ? st_b : st_d;

            s1[r] += dx;
            s9[r] = st;
            s2[r] += SPEED;
            s3[r] += SPEED;
            s0[r] += 1.0f;
            float d13 = s1[r] - s3[r], d24 = s2[r] - s4[r];
            s10[r] = fmaf(d13, d13, d24 * d24);

            stash(r, r == 0 ? sl0 : sl1);
        }
    };

    // Prologue: traj0 -> A  (flushed at ph=0 to cols 18..27)
    #pragma unroll
    for (int r = 0; r < 2; r++) stash(r, myA[r]);
    __syncthreads();

    // Ping-pong: at ph, flush the buffer holding the previous step's traj
    // (ph even: A, ph odd: B) to cols 18+10*ph while computing step ph into
    // the other buffer. Each buffer's read (flush at ph) and next write
    // (do_step at ph+1) are separated by the phase-end barrier.
    #pragma unroll 1
    for (int ph = 0; ph < STEPS; ph++) {
        const float* fbuf = s_rows + ((ph & 1) ? BUFO : 0);
        flush2<10>(out, fbuf, R0, rows_blk, 18 + 10 * ph, t);

        float* w0 = (ph & 1) ? myA[0] : myB[0];
        float* w1 = (ph & 1) ? myA[1] : myB[1];
        do_step(w0, w1);
        __syncthreads();
    }

    // Epilogue. ph=14 (even) wrote step14 into B; A's last reader was the
    // ph=14 flush (fenced by that phase's barrier), so A is free NOW.
    // 1) flush B (step14) -> cols 168..177, and stash final-state head into A
    flush2<10>(out, s_rows + BUFO, R0, rows_blk, 168, t);
    #pragma unroll
    for (int r = 0; r < 2; r++) {
        float* m = myA[r];
        *(float2*)(m + 0)  = make_float2(s0[r], s1[r]);
        *(float2*)(m + 2)  = make_float2(s2[r], s3[r]);
        *(float2*)(m + 4)  = make_float2(s4[r], s5[r]);
        *(float2*)(m + 6)  = make_float2(s6[r], s7[r]);
        *(float2*)(m + 8)  = make_float2(s8[r], s9[r]);
        *(float2*)(m + 10) = make_float2(s10[r], s11[r]);
    }
    __syncthreads();   // B flush complete before B is overwritten

    // 2) stash final-state tail into B
    #pragma unroll
    for (int r = 0; r < 2; r++) {
        float* mb = myB[r];
        *(float2*)(mb + 0) = make_float2(s12[r], s13[r]);
        *(float2*)(mb + 2) = make_float2(s14[r], s15[r]);
        *(float2*)(mb + 4) = make_float2(s16[r], s17[r]);
    }
    __syncthreads();

    // 3) final flush: cols 0..11 from A, cols 12..17 from B
    flush2<12>(out, s_rows, R0, rows_blk, 0, t);
    flush2<6>(out, s_rows + BUFO, R0, rows_blk, 12, t);
}

extern "C" void kernel_launch(void* const* d_in, const int* in_sizes, int n_in,
                              void* d_out, int out_size)
{
    const float* x   = (const float*)d_in[0];
    const float* c1w = (const float*)d_in[1];
    const float* c1b = (const float*)d_in[2];
    const float* c2w = (const float*)d_in[3];
    const float* c2b = (const float*)d_in[4];
    const float* l1w = (const float*)d_in[5];
    const float* l1b = (const float*)d_in[6];
    const float* l2w = (const float*)d_in[7];
    const float* l2b = (const float*)d_in[8];
    float* out = (float*)d_out;

    const int n = in_sizes[0] / NCOLS_IN;
    const int blocks = (n + RPC - 1) / RPC;
    prog_kernel<<<blocks, NT, SMEM_BYTES>>>(x, c1w, c1b, c2w, c2b,
                                            l1w, l1b, l2w, l2b, out, n);
}

// round 15
// speedup vs baseline: 1.3745x; 1.3745x over previous
#include <cuda_runtime.h>

#define NT 128
#define RPC 256                 // rows per CTA (2 per thread)
#define STEPS 15
#define SPEED 5.0f
#define NCOLS_IN 18
#define NCOLS_OUT 178
#define CB 42                   // staged cols per row (40 used); even -> 8B slots
#define SMEM_BYTES (RPC * CB * 4)

// Warp-private flush: warp w flushes rows [32w,32w+32) and [128+32w,+32),
// which are staged exclusively by its own lanes. NC even, compile-time.
template <int NC>
__device__ __forceinline__ void warp_flush(float* __restrict__ out,
                                           const float* __restrict__ stage,
                                           int R0, int rows_blk, int base_col,
                                           int w, int l)
{
    constexpr int NC2 = NC / 2;           // float2 stores per row
    #pragma unroll 1
    for (int g = 0; g < 2; g++) {
        const int lrbase = g * NT + 32 * w;
        #pragma unroll 1
        for (int it = 0; it < NC2; it++) {      // 32 rows * NC2 / 32 lanes
            int idx = it * 32 + l;
            int r = idx / NC2;                  // compile-time -> mul/shift
            int k = idx - r * NC2;
            int lr = lrbase + r;
            if (lr < rows_blk) {
                float2 v = *(const float2*)(stage + lr * CB + 2 * k);
                *(float2*)(out + (long long)(R0 + lr) * NCOLS_OUT + base_col + 2 * k) = v;
            }
        }
    }
}

__global__ void __launch_bounds__(NT) prog_kernel(
    const float* __restrict__ x,
    const float* __restrict__ c1w, const float* __restrict__ c1b,
    const float* __restrict__ c2w, const float* __restrict__ c2b,
    const float* __restrict__ l1w, const float* __restrict__ l1b,
    const float* __restrict__ l2w, const float* __restrict__ l2b,
    float* __restrict__ out, int n)
{
    extern __shared__ float s_rows[];   // RPC * CB staging (warp-owned regions)

    // Pair-packed weights: 16 blocks of 20 floats (80B, 16B-aligned).
    __shared__ float s_w[16 * 20];
    __shared__ float s_cb[12];

    const int t = threadIdx.x;
    const int w = t >> 5, l = t & 31;

    if (t < 32) {
        const int j = t;
        const int base = 20 * (j >> 1) + 10 * (j & 1);
        s_w[base + 0] = l1w[0 * 32 + j];
        s_w[base + 1] = l1w[1 * 32 + j];
        s_w[base + 2] = l1w[2 * 32 + j];
        s_w[base + 3] = l1w[3 * 32 + j];
        s_w[base + 4] = l1b[j];
        s_w[base + 5] = l2w[5 * j + 0];
        s_w[base + 6] = l2w[5 * j + 1];
        s_w[base + 7] = l2w[5 * j + 2];
        s_w[base + 8] = l2w[5 * j + 3];
        s_w[base + 9] = l2w[5 * j + 4];
    } else if (t < 64) {
        const int u = t - 32;
        if (u < 12) {
            float v;
            if      (u == 0) v = c1w[0];
            else if (u == 1) v = c1w[1];
            else if (u == 2) v = c1b[0];
            else if (u == 3) v = c2w[0];
            else if (u == 4) v = c2w[1];
            else if (u == 5) v = c2b[0];
            else if (u < 11) v = l2b[u - 6];
            else             v = 0.0f;
            s_cb[u] = v;
        }
    }
    __syncthreads();   // the ONLY block-wide barrier

    const int R0 = blockIdx.x * RPC;
    int rows_blk = n - R0; if (rows_blk > RPC) rows_blk = RPC;

    const float c1w0 = s_cb[0], c1w1 = s_cb[1], c1b0 = s_cb[2];
    const float c2w0 = s_cb[3], c2w1 = s_cb[4], c2b0 = s_cb[5];
    const float l2b0 = s_cb[6], l2b1 = s_cb[7], l2b2 = s_cb[8];
    const float l2b3 = s_cb[9], l2b4 = s_cb[10];

    float s0[2], s1[2], s2[2], s3[2], s4[2], s5[2], s6[2], s7[2], s8[2],
          s9[2], s10[2], s11[2], s12[2], s13[2], s14[2], s15[2], s16[2], s17[2];
    float* my[2];

    #pragma unroll
    for (int r = 0; r < 2; r++) {
        const int lr = t + r * NT;
        const int row = R0 + ((lr < rows_blk) ? lr : 0);
        my[r] = s_rows + lr * CB;
        const float* xr = x + (long long)row * NCOLS_IN;
        float2 v0 = *(const float2*)(xr + 0);
        float2 v1 = *(const float2*)(xr + 2);
        float2 v2 = *(const float2*)(xr + 4);
        float2 v3 = *(const float2*)(xr + 6);
        float2 v4 = *(const float2*)(xr + 8);
        float2 v8 = *(const float2*)(xr + 16);
        s0[r] = v0.x; s1[r] = v0.y; s2[r] = v1.x; s3[r] = v1.y;
        s4[r] = v2.x; s5[r] = v2.y; s6[r] = v3.x; s7[r] = v3.y;
        s8[r] = v4.x; s9[r] = v4.y; s17[r] = v8.y;
        float d13 = s1[r] - s3[r], d24 = s2[r] - s4[r];
        s10[r] = fmaf(d13, d13, d24 * d24);
        s11[r] = s12[r] = s13[r] = s14[r] = s15[r] = s16[r] = 0.0f;
    }

    auto stash = [&](int r, float* slot) {
        *(float2*)(slot + 0) = make_float2(s10[r], s1[r]);
        *(float2*)(slot + 2) = make_float2(s2[r], s3[r]);
        *(float2*)(slot + 4) = make_float2(s4[r], s5[r]);
        *(float2*)(slot + 6) = make_float2(s6[r], s7[r]);
        *(float2*)(slot + 8) = make_float2(s8[r], s17[r]);
    };

    auto do_step = [&](int slot_off) {
        float h20[2], h21[2], h22[2], h23[2];
        float p0[2], p1[2], p2[2], p3[2], p4[2];

        #pragma unroll
        for (int r = 0; r < 2; r++) {
            const float f0 = s1[r], f1 = s2[r], f2 = s3[r], f3 = s4[r],
                        f4 = s9[r], f5 = s17[r];
            float h10 = fmaxf(fmaf(c1w1, f1, fmaf(c1w0, f0, c1b0)), 0.0f);
            float h11 = fmaxf(fmaf(c1w1, f2, fmaf(c1w0, f1, c1b0)), 0.0f);
            float h12 = fmaxf(fmaf(c1w1, f3, fmaf(c1w0, f2, c1b0)), 0.0f);
            float h13 = fmaxf(fmaf(c1w1, f4, fmaf(c1w0, f3, c1b0)), 0.0f);
            float h14 = fmaxf(fmaf(c1w1, f5, fmaf(c1w0, f4, c1b0)), 0.0f);
            h20[r] = fmaxf(fmaf(c2w1, h11, fmaf(c2w0, h10, c2b0)), 0.0f);
            h21[r] = fmaxf(fmaf(c2w1, h12, fmaf(c2w0, h11, c2b0)), 0.0f);
            h22[r] = fmaxf(fmaf(c2w1, h13, fmaf(c2w0, h12, c2b0)), 0.0f);
            h23[r] = fmaxf(fmaf(c2w1, h14, fmaf(c2w0, h13, c2b0)), 0.0f);
            p0[r] = l2b0; p1[r] = l2b1; p2[r] = l2b2; p3[r] = l2b3; p4[r] = l2b4;
        }

        #pragma unroll 8
        for (int q = 0; q < 16; q++) {
            const float4 a0 = *(const float4*)(s_w + 20 * q + 0);
            const float4 a1 = *(const float4*)(s_w + 20 * q + 4);
            const float4 a2 = *(const float4*)(s_w + 20 * q + 8);
            const float4 a3 = *(const float4*)(s_w + 20 * q + 12);
            const float4 a4 = *(const float4*)(s_w + 20 * q + 16);

            #pragma unroll
            for (int r = 0; r < 2; r++) {
                float h3a = fmaf(h23[r], a0.w,
                            fmaf(h22[r], a0.z,
                            fmaf(h21[r], a0.y,
                            fmaf(h20[r], a0.x, a1.x))));
                h3a = fmaxf(h3a, 0.0f);
                p0[r] = fmaf(h3a, a1.y, p0[r]);
                p1[r] = fmaf(h3a, a1.z, p1[r]);
                p2[r] = fmaf(h3a, a1.w, p2[r]);
                p3[r] = fmaf(h3a, a2.x, p3[r]);
                p4[r] = fmaf(h3a, a2.y, p4[r]);

                float h3b = fmaf(h23[r], a3.y,
                            fmaf(h22[r], a3.x,
                            fmaf(h21[r], a2.w,
                            fmaf(h20[r], a2.z, a3.z))));
                h3b = fmaxf(h3b, 0.0f);
                p0[r] = fmaf(h3b, a3.w, p0[r]);
                p1[r] = fmaf(h3b, a4.x, p1[r]);
                p2[r] = fmaf(h3b, a4.y, p2[r]);
                p3[r] = fmaf(h3b, a4.z, p3[r]);
                p4[r] = fmaf(h3b, a4.w, p4[r]);
            }
        }

        #pragma unroll
        for (int r = 0; r < 2; r++) {
            float q0 = 1.0f / (1.0f + expf(-p0[r]));
            float q1 = 1.0f / (1.0f + expf(-p1[r]));
            float q2 = 1.0f / (1.0f + expf(-p2[r]));
            float q3 = 1.0f / (1.0f + expf(-p3[r]));
            float q4 = 1.0f / (1.0f + expf(-p4[r]));

            s5[r] = q0; s6[r] = q1; s7[r] = q2; s8[r] = q3; s17[r] = q4;

            const float a = q1 - q0, b = q2 - q0, c = q3 - q0;
            const float d = q2 - q1, e = q3 - q1, f = q3 - q2;
            s11[r] = a; s12[r] = b; s13[r] = c;
            s14[r] = d; s15[r] = e; s16[r] = f;

            const float dx_c = (c <= 0.0f) ? 0.0f : SPEED;
            const float st_c = (c <= 0.0f) ? 0.0f : 3.0f;
            const float dx_f = (f <= 0.0f) ? 0.0f : SPEED;
            const float st_f = (f <= 0.0f) ? 2.0f : 3.0f;
            const float dx_e = (e <= 0.0f) ? -SPEED : SPEED;
            const float st_e = (e <= 0.0f) ? 1.0f : 3.0f;
            const float dx_b = (b <= 0.0f) ? dx_c : dx_f;
            const float st_b = (b <= 0.0f) ? st_c : st_f;
            const float dx_d = (d <= 0.0f) ? dx_e : dx_f;
            const float st_d = (d <= 0.0f) ? st_e : st_f;
            const float dx   = (a <= 0.0f) ? dx_b : dx_d;
            const float st   = (a <= 0.0f) ? st_b : st_d;

            s1[r] += dx;
            s9[r] = st;
            s2[r] += SPEED;
            s3[r] += SPEED;
            s0[r] += 1.0f;
            float d13 = s1[r] - s3[r], d24 = s2[r] - s4[r];
            s10[r] = fmaf(d13, d13, d24 * d24);

            stash(r, my[r] + slot_off);
        }
    };

    // Phase 1: traj0 (slots 0..9) + steps 0..2 -> cols 18..57
    #pragma unroll
    for (int r = 0; r < 2; r++) stash(r, my[r]);
    #pragma unroll 1
    for (int step = 0; step < 3; step++)
        do_step(10 * (step + 1));
    __syncwarp();
    warp_flush<40>(out, s_rows, R0, rows_blk, 18, w, l);
    __syncwarp();

    // Phases 2..4: steps (3..6), (7..10), (11..14) -> 40 cols each
    #pragma unroll 1
    for (int ph = 0; ph < 3; ph++) {
        #pragma unroll 1
        for (int step = 0; step < 4; step++)
            do_step(10 * step);
        __syncwarp();
        warp_flush<40>(out, s_rows, R0, rows_blk, 58 + 40 * ph, w, l);
        __syncwarp();
    }

    // Phase 5: final state (18 cols) -> cols 0..17
    #pragma unroll
    for (int r = 0; r < 2; r++) {
        float* m = my[r];
        *(float2*)(m + 0)  = make_float2(s0[r], s1[r]);
        *(float2*)(m + 2)  = make_float2(s2[r], s3[r]);
        *(float2*)(m + 4)  = make_float2(s4[r], s5[r]);
        *(float2*)(m + 6)  = make_float2(s6[r], s7[r]);
        *(float2*)(m + 8)  = make_float2(s8[r], s9[r]);
        *(float2*)(m + 10) = make_float2(s10[r], s11[r]);
        *(float2*)(m + 12) = make_float2(s12[r], s13[r]);
        *(float2*)(m + 14) = make_float2(s14[r], s15[r]);
        *(float2*)(m + 16) = make_float2(s16[r], s17[r]);
    }
    __syncwarp();
    warp_flush<18>(out, s_rows, R0, rows_blk, 0, w, l);
}

extern "C" void kernel_launch(void* const* d_in, const int* in_sizes, int n_in,
                              void* d_out, int out_size)
{
    const float* x   = (const float*)d_in[0];
    const float* c1w = (const float*)d_in[1];
    const float* c1b = (const float*)d_in[2];
    const float* c2w = (const float*)d_in[3];
    const float* c2b = (const float*)d_in[4];
    const float* l1w = (const float*)d_in[5];
    const float* l1b = (const float*)d_in[6];
    const float* l2w = (const float*)d_in[7];
    const float* l2b = (const float*)d_in[8];
    float* out = (float*)d_out;

    const int n = in_sizes[0] / NCOLS_IN;
    const int blocks = (n + RPC - 1) / RPC;
    prog_kernel<<<blocks, NT, SMEM_BYTES>>>(x, c1w, c1b, c2w, c2b,
                                            l1w, l1b, l2w, l2b, out, n);
}

// round 16
// speedup vs baseline: 1.5428x; 1.1224x over previous
#include <cuda_runtime.h>

#define NT 128
#define RPC 256                 // rows per CTA (2 per thread)
#define STEPS 15
#define SPEED 5.0f
#define NCOLS_IN 18
#define NCOLS_OUT 178
#define CB 42                   // staged cols per row (40 used); even -> 8B slots
#define SMEM_BYTES (RPC * CB * 4)

// Packed dual-FMA: d = a*b + c per 32-bit lane (FFMA2). Bit-exact vs 2x fmaf.
__device__ __forceinline__ float2 ffma2(float2 a, float2 b, float2 c)
{
    unsigned long long ua = reinterpret_cast<unsigned long long&>(a);
    unsigned long long ub = reinterpret_cast<unsigned long long&>(b);
    unsigned long long uc = reinterpret_cast<unsigned long long&>(c);
    unsigned long long ud;
    asm("fma.rn.f32x2 %0, %1, %2, %3;" : "=l"(ud) : "l"(ua), "l"(ub), "l"(uc));
    return reinterpret_cast<float2&>(ud);
}

__device__ __forceinline__ float2 relu2(float2 v)
{
    v.x = fmaxf(v.x, 0.0f);
    v.y = fmaxf(v.y, 0.0f);
    return v;
}

template <int NC>
__device__ __forceinline__ void flush2(float* __restrict__ out,
                                       const float* __restrict__ stage,
                                       int R0, int rows_blk, int base_col, int t)
{
    constexpr int NC2 = NC / 2;          // NC even
    const unsigned total = (unsigned)rows_blk * NC2;
    for (unsigned idx = t; idx < total; idx += NT) {
        unsigned r = idx / NC2;
        unsigned k = idx - r * NC2;
        float2 v = *(const float2*)(stage + r * CB + 2 * k);
        *(float2*)(out + (long long)(R0 + r) * NCOLS_OUT + base_col + 2 * k) = v;
    }
}

__global__ void __launch_bounds__(NT) prog_kernel(
    const float* __restrict__ x,
    const float* __restrict__ c1w, const float* __restrict__ c1b,
    const float* __restrict__ c2w, const float* __restrict__ c2b,
    const float* __restrict__ l1w, const float* __restrict__ l1b,
    const float* __restrict__ l2w, const float* __restrict__ l2b,
    float* __restrict__ out, int n)
{
    extern __shared__ float s_rows[];   // RPC * CB staging

    // Neuron-pair interleaved weights: 16 blocks of 20 floats (80B, 16B-aligned).
    // Block q, neurons j0=2q, j1=2q+1:
    //  [0..1] (l1w[0][j0], l1w[0][j1])  [2..3] l1w[1] pair
    //  [4..5] l1w[2] pair               [6..7] l1w[3] pair
    //  [8..9] (l1b[j0], l1b[j1])
    //  [10..11] l2w[.][0] pair ... [18..19] l2w[.][4] pair
    __shared__ __align__(16) float s_w[16 * 20];
    __shared__ float s_cb[12];

    const int t = threadIdx.x;
    if (t < 32) {
        const int j = t;
        const int base = 20 * (j >> 1) + (j & 1);
        s_w[base + 0]  = l1w[0 * 32 + j];
        s_w[base + 2]  = l1w[1 * 32 + j];
        s_w[base + 4]  = l1w[2 * 32 + j];
        s_w[base + 6]  = l1w[3 * 32 + j];
        s_w[base + 8]  = l1b[j];
        s_w[base + 10] = l2w[5 * j + 0];
        s_w[base + 12] = l2w[5 * j + 1];
        s_w[base + 14] = l2w[5 * j + 2];
        s_w[base + 16] = l2w[5 * j + 3];
        s_w[base + 18] = l2w[5 * j + 4];
    } else if (t < 64) {
        const int u = t - 32;
        if (u < 12) {
            float v;
            if      (u == 0) v = c1w[0];
            else if (u == 1) v = c1w[1];
            else if (u == 2) v = c1b[0];
            else if (u == 3) v = c2w[0];
            else if (u == 4) v = c2w[1];
            else if (u == 5) v = c2b[0];
            else if (u < 11) v = l2b[u - 6];
            else             v = 0.0f;
            s_cb[u] = v;
        }
    }
    __syncthreads();

    const int R0 = blockIdx.x * RPC;
    int rows_blk = n - R0; if (rows_blk > RPC) rows_blk = RPC;

    // packed (w,w) conv weights
    const float2 c1w0p = make_float2(s_cb[0], s_cb[0]);
    const float2 c1w1p = make_float2(s_cb[1], s_cb[1]);
    const float2 c1bp  = make_float2(s_cb[2], s_cb[2]);
    const float2 c2w0p = make_float2(s_cb[3], s_cb[3]);
    const float2 c2w1p = make_float2(s_cb[4], s_cb[4]);
    const float2 c2bp  = make_float2(s_cb[5], s_cb[5]);
    const float l2b0 = s_cb[6], l2b1 = s_cb[7], l2b2 = s_cb[8];
    const float l2b3 = s_cb[9], l2b4 = s_cb[10];

    float s0[2], s1[2], s2[2], s3[2], s4[2], s5[2], s6[2], s7[2], s8[2],
          s9[2], s10[2], s11[2], s12[2], s13[2], s14[2], s15[2], s16[2], s17[2];
    float* my[2];

    #pragma unroll
    for (int r = 0; r < 2; r++) {
        const int lr = t + r * NT;
        const int row = R0 + ((lr < rows_blk) ? lr : 0);
        my[r] = s_rows + lr * CB;
        const float* xr = x + (long long)row * NCOLS_IN;
        float2 v0 = *(const float2*)(xr + 0);
        float2 v1 = *(const float2*)(xr + 2);
        float2 v2 = *(const float2*)(xr + 4);
        float2 v3 = *(const float2*)(xr + 6);
        float2 v4 = *(const float2*)(xr + 8);
        float2 v8 = *(const float2*)(xr + 16);
        s0[r] = v0.x; s1[r] = v0.y; s2[r] = v1.x; s3[r] = v1.y;
        s4[r] = v2.x; s5[r] = v2.y; s6[r] = v3.x; s7[r] = v3.y;
        s8[r] = v4.x; s9[r] = v4.y; s17[r] = v8.y;
        float d13 = s1[r] - s3[r], d24 = s2[r] - s4[r];
        s10[r] = fmaf(d13, d13, d24 * d24);
        s11[r] = s12[r] = s13[r] = s14[r] = s15[r] = s16[r] = 0.0f;
    }

    auto stash = [&](int r, float* slot) {
        *(float2*)(slot + 0) = make_float2(s10[r], s1[r]);
        *(float2*)(slot + 2) = make_float2(s2[r], s3[r]);
        *(float2*)(slot + 4) = make_float2(s4[r], s5[r]);
        *(float2*)(slot + 6) = make_float2(s6[r], s7[r]);
        *(float2*)(slot + 8) = make_float2(s8[r], s17[r]);
    };

    auto do_step = [&](int slot_off) {
        // Packed head: lanes = the two rows.
        float2 h2p0[2], h2p1[2], h2p2[2], h2p3[2];
        float2 pp0[2], pp1[2], pp2[2], pp3[2], pp4[2];

        #pragma unroll
        for (int r = 0; r < 2; r++) {
            // NOTE: here lanes are (row r only) — pack features per row pair-wise
            // across the two rows instead:
            (void)r;
        }
        {
            const float2 fp0 = make_float2(s1[0],  s1[1]);
            const float2 fp1 = make_float2(s2[0],  s2[1]);
            const float2 fp2 = make_float2(s3[0],  s3[1]);
            const float2 fp3 = make_float2(s4[0],  s4[1]);
            const float2 fp4 = make_float2(s9[0],  s9[1]);
            const float2 fp5 = make_float2(s17[0], s17[1]);

            float2 h10 = relu2(ffma2(c1w1p, fp1, ffma2(c1w0p, fp0, c1bp)));
            float2 h11 = relu2(ffma2(c1w1p, fp2, ffma2(c1w0p, fp1, c1bp)));
            float2 h12 = relu2(ffma2(c1w1p, fp3, ffma2(c1w0p, fp2, c1bp)));
            float2 h13 = relu2(ffma2(c1w1p, fp4, ffma2(c1w0p, fp3, c1bp)));
            float2 h14 = relu2(ffma2(c1w1p, fp5, ffma2(c1w0p, fp4, c1bp)));

            float2 h20 = relu2(ffma2(c2w1p, h11, ffma2(c2w0p, h10, c2bp)));
            float2 h21 = relu2(ffma2(c2w1p, h12, ffma2(c2w0p, h11, c2bp)));
            float2 h22 = relu2(ffma2(c2w1p, h13, ffma2(c2w0p, h12, c2bp)));
            float2 h23 = relu2(ffma2(c2w1p, h14, ffma2(c2w0p, h13, c2bp)));

            // re-broadcast per row: lane pair = (h2k[row], h2k[row])
            h2p0[0] = make_float2(h20.x, h20.x); h2p0[1] = make_float2(h20.y, h20.y);
            h2p1[0] = make_float2(h21.x, h21.x); h2p1[1] = make_float2(h21.y, h21.y);
            h2p2[0] = make_float2(h22.x, h22.x); h2p2[1] = make_float2(h22.y, h22.y);
            h2p3[0] = make_float2(h23.x, h23.x); h2p3[1] = make_float2(h23.y, h23.y);
        }

        #pragma unroll
        for (int r = 0; r < 2; r++) {
            pp0[r] = make_float2(l2b0, 0.0f);
            pp1[r] = make_float2(l2b1, 0.0f);
            pp2[r] = make_float2(l2b2, 0.0f);
            pp3[r] = make_float2(l2b3, 0.0f);
            pp4[r] = make_float2(l2b4, 0.0f);
        }

        // Inner loop: lanes = neuron pair (2q, 2q+1); weights shared across rows.
        #pragma unroll 4
        for (int q = 0; q < 16; q++) {
            const float4 A = *(const float4*)(s_w + 20 * q + 0);   // l1w k0,k1 pairs
            const float4 B = *(const float4*)(s_w + 20 * q + 4);   // l1w k2,k3 pairs
            const float4 C = *(const float4*)(s_w + 20 * q + 8);   // bias pair, u0 pair
            const float4 D = *(const float4*)(s_w + 20 * q + 12);  // u1, u2 pairs
            const float4 E = *(const float4*)(s_w + 20 * q + 16);  // u3, u4 pairs
            const float2 k0 = make_float2(A.x, A.y);
            const float2 k1 = make_float2(A.z, A.w);
            const float2 k2 = make_float2(B.x, B.y);
            const float2 k3 = make_float2(B.z, B.w);
            const float2 bi = make_float2(C.x, C.y);
            const float2 u0 = make_float2(C.z, C.w);
            const float2 u1 = make_float2(D.x, D.y);
            const float2 u2 = make_float2(D.z, D.w);
            const float2 u3 = make_float2(E.x, E.y);
            const float2 u4 = make_float2(E.z, E.w);

            #pragma unroll
            for (int r = 0; r < 2; r++) {
                float2 h3 = ffma2(h2p3[r], k3,
                           ffma2(h2p2[r], k2,
                           ffma2(h2p1[r], k1,
                           ffma2(h2p0[r], k0, bi))));
                h3 = relu2(h3);
                pp0[r] = ffma2(h3, u0, pp0[r]);
                pp1[r] = ffma2(h3, u1, pp1[r]);
                pp2[r] = ffma2(h3, u2, pp2[r]);
                pp3[r] = ffma2(h3, u3, pp3[r]);
                pp4[r] = ffma2(h3, u4, pp4[r]);
            }
        }

        #pragma unroll
        for (int r = 0; r < 2; r++) {
            float p0 = pp0[r].x + pp0[r].y;
            float p1 = pp1[r].x + pp1[r].y;
            float p2 = pp2[r].x + pp2[r].y;
            float p3 = pp3[r].x + pp3[r].y;
            float p4 = pp4[r].x + pp4[r].y;

            // sigmoid, full precision
            float q0 = 1.0f / (1.0f + expf(-p0));
            float q1 = 1.0f / (1.0f + expf(-p1));
            float q2 = 1.0f / (1.0f + expf(-p2));
            float q3 = 1.0f / (1.0f + expf(-p3));
            float q4 = 1.0f / (1.0f + expf(-p4));

            s5[r] = q0; s6[r] = q1; s7[r] = q2; s8[r] = q3; s17[r] = q4;

            const float a = q1 - q0, b = q2 - q0, c = q3 - q0;
            const float d = q2 - q1, e = q3 - q1, f = q3 - q2;
            s11[r] = a; s12[r] = b; s13[r] = c;
            s14[r] = d; s15[r] = e; s16[r] = f;

            const float dx_c = (c <= 0.0f) ? 0.0f : SPEED;
            const float st_c = (c <= 0.0f) ? 0.0f : 3.0f;
            const float dx_f = (f <= 0.0f) ? 0.0f : SPEED;
            const float st_f = (f <= 0.0f) ? 2.0f : 3.0f;
            const float dx_e = (e <= 0.0f) ? -SPEED : SPEED;
            const float st_e = (e <= 0.0f) ? 1.0f : 3.0f;
            const float dx_b = (b <= 0.0f) ? dx_c : dx_f;
            const float st_b = (b <= 0.0f) ? st_c : st_f;
            const float dx_d = (d <= 0.0f) ? dx_e : dx_f;
            const float st_d = (d <= 0.0f) ? st_e : st_f;
            const float dx   = (a <= 0.0f) ? dx_b : dx_d;
            const float st   = (a <= 0.0f) ? st_b : st_d;

            s1[r] += dx;
            s9[r] = st;
            s2[r] += SPEED;
            s3[r] += SPEED;
            s0[r] += 1.0f;
            float d13 = s1[r] - s3[r], d24 = s2[r] - s4[r];
            s10[r] = fmaf(d13, d13, d24 * d24);

            stash(r, my[r] + slot_off);
        }
    };

    // Phase 1: traj0 (slots 0..9) + steps 0..2 -> cols 18..57
    #pragma unroll
    for (int r = 0; r < 2; r++) stash(r, my[r]);
    #pragma unroll 1
    for (int step = 0; step < 3; step++)
        do_step(10 * (step + 1));
    __syncthreads();
    flush2<40>(out, s_rows, R0, rows_blk, 18, t);
    __syncthreads();

    // Phase 2: steps 3..6 -> cols 58..97
    #pragma unroll 1
    for (int step = 3; step < 7; step++)
        do_step(10 * (step - 3));
    __syncthreads();
    flush2<40>(out, s_rows, R0, rows_blk, 58, t);
    __syncthreads();

    // Phase 3: steps 7..10 -> cols 98..137
    #pragma unroll 1
    for (int step = 7; step < 11; step++)
        do_step(10 * (step - 7));
    __syncthreads();
    flush2<40>(out, s_rows, R0, rows_blk, 98, t);
    __syncthreads();

    // Phase 4: steps 11..14 -> cols 138..177
    #pragma unroll 1
    for (int step = 11; step < 15; step++)
        do_step(10 * (step - 11));
    __syncthreads();
    flush2<40>(out, s_rows, R0, rows_blk, 138, t);
    __syncthreads();

    // Phase 5: final state (18 cols) -> cols 0..17
    #pragma unroll
    for (int r = 0; r < 2; r++) {
        float* m = my[r];
        *(float2*)(m + 0)  = make_float2(s0[r], s1[r]);
        *(float2*)(m + 2)  = make_float2(s2[r], s3[r]);
        *(float2*)(m + 4)  = make_float2(s4[r], s5[r]);
        *(float2*)(m + 6)  = make_float2(s6[r], s7[r]);
        *(float2*)(m + 8)  = make_float2(s8[r], s9[r]);
        *(float2*)(m + 10) = make_float2(s10[r], s11[r]);
        *(float2*)(m + 12) = make_float2(s12[r], s13[r]);
        *(float2*)(m + 14) = make_float2(s14[r], s15[r]);
        *(float2*)(m + 16) = make_float2(s16[r], s17[r]);
    }
    __syncthreads();
    flush2<18>(out, s_rows, R0, rows_blk, 0, t);
}

extern "C" void kernel_launch(void* const* d_in, const int* in_sizes, int n_in,
                              void* d_out, int out_size)
{
    const float* x   = (const float*)d_in[0];
    const float* c1w = (const float*)d_in[1];
    const float* c1b = (const float*)d_in[2];
    const float* c2w = (const float*)d_in[3];
    const float* c2b = (const float*)d_in[4];
    const float* l1w = (const float*)d_in[5];
    const float* l1b = (const float*)d_in[6];
    const float* l2w = (const float*)d_in[7];
    const float* l2b = (const float*)d_in[8];
    float* out = (float*)d_out;

    const int n = in_sizes[0] / NCOLS_IN;
    const int blocks = (n + RPC - 1) / RPC;
    prog_kernel<<<blocks, NT, SMEM_BYTES>>>(x, c1w, c1b, c2w, c2b,
                                            l1w, l1b, l2w, l2b, out, n);
}